// round 17
// baseline (speedup 1.0000x reference)
#include <cuda_runtime.h>
#include <math.h>

#define NP 10000
#define NG 1000
#define NC 80
#define PMAX 2500
#define NITER ((NP + 255) / 256)   // 40

// ---- persistent device scratch ----
__device__ float  g_cost[(size_t)NG * NP];   // column-major: [j][i]
__device__ float  g_cls [(size_t)NC * NP];   // transposed cls cost table
__device__ float4 g_pn  [NP];                // pred boxes / factor
__device__ float4 g_pc  [NP];                // (pcx, pcy, area, vadd)
__device__ int    g_rowcnt[NP];
__device__ int    g_minGt [NP];
__device__ int    g_priorFlag[NP];
__device__ int    g_colcnt[NG];
__device__ int    g_cand[NG * 5];
__device__ int    g_dk[NG];
__device__ int    g_priorCount;
__device__ int    g_priorList[PMAX];
__device__ int    g_priorCur [PMAX];
__device__ float  g_priorCost[(size_t)PMAX * NG];

__device__ __forceinline__ float cls_cost_f(float x) {
    float p   = (x >= 0.f) ? (1.f / (1.f + expf(-x))) : (expf(x) / (1.f + expf(x)));
    float omp = 1.f - p;
    float pos = -logf(p + 1e-12f) * 0.25f * (omp * omp);
    float neg = -log1pf(-(p - 1e-12f)) * 0.75f * (p * p);
    return (pos - neg) * 2.0f;
}

__device__ __forceinline__ bool cost_less(float av, int ai, float bv, int bi) {
    return (av < bv) || (av == bv && ai < bi);
}

// cls table + init fused (cq==0 slice does the init; no ordering hazard).
__global__ void cls_kernel(const float* __restrict__ logits) {
    int i  = blockIdx.x * blockDim.x + threadIdx.x;
    int cq = blockIdx.y;
    if (i >= NP) return;
    if (cq == 0) {
        g_rowcnt[i] = 0; g_priorFlag[i] = 0; g_minGt[i] = 0x7fffffff;
        if (i < NG) g_colcnt[i] = 0;
        if (i == 0) g_priorCount = 0;
    }
    float4 v = *reinterpret_cast<const float4*>(logits + (size_t)i * NC + cq * 4);
    g_cls[(size_t)(cq * 4 + 0) * NP + i] = cls_cost_f(v.x);
    g_cls[(size_t)(cq * 4 + 1) * NP + i] = cls_cost_f(v.y);
    g_cls[(size_t)(cq * 4 + 2) * NP + i] = cls_cost_f(v.z);
    g_cls[(size_t)(cq * 4 + 3) * NP + i] = cls_cost_f(v.w);
}

// warp per pred: ballot validity + normalized box + per-pred precompute.
__global__ void valid_kernel(const float* __restrict__ pb, const float* __restrict__ gb,
                             const int* __restrict__ p_h, const int* __restrict__ p_w) {
    int wid  = threadIdx.x >> 5, lane = threadIdx.x & 31;
    int i = blockIdx.x * 8 + wid;
    if (i >= NP) return;
    float fw = (float)(*p_w), fh = (float)(*p_h);
    float4 p = reinterpret_cast<const float4*>(pb)[i];
    float pcx = (p.x + p.z) * 0.5f, pcy = (p.y + p.w) * 0.5f;

    int valid = 0;
    for (int jb = 0; jb < NG; jb += 32) {
        float4 g = reinterpret_cast<const float4*>(gb)[jb + lane];
        bool ib = (pcx > g.x) && (pcx < g.z) && (pcy > g.y) && (pcy < g.w);
        float gcx = (g.x + g.z) * 0.5f, gcy = (g.y + g.w) * 0.5f;
        float gw = g.z - g.x, gh = g.w - g.y;
        bool ic = (pcx > gcx - 2.5f * gw) && (pcx < gcx + 2.5f * gw) &&
                  (pcy > gcy - 2.5f * gh) && (pcy < gcy + 2.5f * gh);
        unsigned hit = __ballot_sync(0xffffffffu, ib || ic);
        if (hit) { valid = 1; break; }
    }
    if (lane == 0) {
        float4 pn;
        pn.x = p.x / fw; pn.y = p.y / fh; pn.z = p.z / fw; pn.w = p.w / fh;
        g_pn[i] = pn;
        float4 pc;
        pc.x = pcx; pc.y = pcy;
        pc.z = (p.z - p.x) * (p.w - p.y);
        pc.w = valid ? 0.0f : 10000.0f;
        g_pc[i] = pc;
    }
}

__device__ __forceinline__ void merge_lists(float* aio, float* acv, int* aci,
                                            const float* bio, const float* bcv, const int* bci) {
    float rio[5];
    { int ia = 0, ib = 0;
      #pragma unroll
      for (int q = 0; q < 5; q++) rio[q] = (aio[ia] >= bio[ib]) ? aio[ia++] : bio[ib++];
    }
    float rcv[5]; int rci[5];
    { int ia = 0, ib = 0;
      #pragma unroll
      for (int q = 0; q < 5; q++) {
          if (cost_less(acv[ia], aci[ia], bcv[ib], bci[ib])) { rcv[q] = acv[ia]; rci[q] = aci[ia]; ia++; }
          else                                               { rcv[q] = bcv[ib]; rci[q] = bci[ib]; ib++; }
      }
    }
    #pragma unroll
    for (int q = 0; q < 5; q++) { aio[q] = rio[q]; acv[q] = rcv[q]; aci[q] = rci[q]; }
}

// ONE gt per block. Warp-replicated top-5 lists: per-iteration cost is one
// compare + ballot; the insert network runs rarely (warp-global 5th is a
// 32x tighter threshold than per-thread) and UNIFORMLY (no divergence).
// Exactness: the set of 5 best (value,idx)-lexicographic entries of a
// multiset is insertion-order independent; sentinels can never win.
__global__ void __launch_bounds__(256, 4)
pair_kernel(const float* __restrict__ pb, const float* __restrict__ gb,
            const int* __restrict__ labels,
            const int* __restrict__ p_h, const int* __restrict__ p_w) {
    int j = blockIdx.x;
    __shared__ float s_io[8 * 5];
    __shared__ float s_cv[8 * 5];
    __shared__ int   s_ci[8 * 5];

    float fw = (float)(*p_w), fh = (float)(*p_h);
    float4 g = reinterpret_cast<const float4*>(gb)[j];
    int lab = labels[j];
    float gx1 = g.x, gy1 = g.y, gx2 = g.z, gy2 = g.w;
    float ag  = (gx2 - gx1) * (gy2 - gy1);
    float gcx = (gx1 + gx2) * 0.5f, gcy = (gy1 + gy2) * 0.5f;
    float gw  = gx2 - gx1, gh = gy2 - gy1;
    float n0 = gx1 / fw, n1 = gy1 / fh, n2 = gx2 / fw, n3 = gy2 / fh;
    float wx_lo = fmaxf(gx1, gcx - 2.5f * gw), wx_hi = fminf(gx2, gcx + 2.5f * gw);
    float wy_lo = fmaxf(gy1, gcy - 2.5f * gh), wy_hi = fminf(gy2, gcy + 2.5f * gh);
    const float* __restrict__ clsCol  = g_cls + (size_t)lab * NP;
    float*       __restrict__ costCol = g_cost + (size_t)j * NP;

    int wid = threadIdx.x >> 5, lane = threadIdx.x & 31;

    // warp-replicated lists
    float i0 = -3.4e38f, i1 = -3.4e38f, i2 = -3.4e38f, i3 = -3.4e38f, i4 = -3.4e38f;
    float c0 = 3.4e38f, c1 = 3.4e38f, c2 = 3.4e38f, c3 = 3.4e38f, c4v = 3.4e38f;
    int   x0 = 0x7fffffff, x1 = 0x7fffffff, x2 = 0x7fffffff, x3 = 0x7fffffff, x4 = 0x7fffffff;

#define WINS_IOU(v) do { float _v = (v);                                             \
    if (_v > i4) { i4 = _v;                                                          \
        if (i4 > i3) { float _t = i3; i3 = i4; i4 = _t;                              \
            if (i3 > i2) { _t = i2; i2 = i3; i3 = _t;                                \
                if (i2 > i1) { _t = i1; i1 = i2; i2 = _t;                            \
                    if (i1 > i0) { _t = i0; i0 = i1; i1 = _t; } } } } } } while (0)

#define WINS_COST(v, vx) do { float _v = (v); int _i = (vx);                         \
    if (cost_less(_v, _i, c4v, x4)) { c4v = _v; x4 = _i;                             \
        if (cost_less(c4v, x4, c3, x3)) { float _t = c3; c3 = c4v; c4v = _t; int _u = x3; x3 = x4; x4 = _u; \
            if (cost_less(c3, x3, c2, x2)) { _t = c2; c2 = c3; c3 = _t; _u = x2; x2 = x3; x3 = _u; \
                if (cost_less(c2, x2, c1, x1)) { _t = c1; c1 = c2; c2 = _t; _u = x1; x1 = x2; x2 = _u; \
                    if (cost_less(c1, x1, c0, x0)) { _t = c0; c0 = c1; c1 = _t; _u = x0; x0 = x1; x1 = _u; } } } } } } while (0)

    for (int it = 0; it < NITER; it++) {
        int baseW = it * 256 + wid * 32;
        if (baseW >= NP) break;              // warp-uniform
        int i = baseW + lane;
        bool live = i < NP;

        float iou = -3.4e38f;
        float cost = 3.4e38f;
        if (live) {
            float4 p  = reinterpret_cast<const float4*>(pb)[i];
            float4 pn = g_pn[i];
            float4 pc = g_pc[i];
            float  cv = clsCol[i];

            float ltx = fmaxf(p.x, gx1), lty = fmaxf(p.y, gy1);
            float rbx = fminf(p.z, gx2), rby = fminf(p.w, gy2);
            float iw = fmaxf(rbx - ltx, 0.f), ih = fmaxf(rby - lty, 0.f);
            float inter = iw * ih;
            float uni = pc.z + ag - inter;
            iou = inter / uni;
            float ex = fmaxf(p.z, gx2) - fminf(p.x, gx1);
            float ey = fmaxf(p.w, gy2) - fminf(p.y, gy1);
            float enc = ex * ey;
            float giou = iou - (enc - uni) / enc;
            float l1 = fabsf(pn.x - n0) + fabsf(pn.y - n1) +
                       fabsf(pn.z - n2) + fabsf(pn.w - n3);
            cost = cv + l1 * 5.0f + (-giou * 2.0f);
            bool ok = (pc.x > wx_lo) && (pc.x < wx_hi) && (pc.y > wy_lo) && (pc.y < wy_hi);
            cost = cost + (ok ? 0.0f : 100.0f);
            cost = cost + pc.w;
            costCol[i] = cost;
        }

        unsigned mio = __ballot_sync(0xffffffffu, iou > i4);
        while (mio) {
            int src = __ffs(mio) - 1; mio &= mio - 1;
            float v = __shfl_sync(0xffffffffu, iou, src);
            WINS_IOU(v);
        }
        unsigned mco = __ballot_sync(0xffffffffu, cost_less(cost, i, c4v, x4));
        while (mco) {
            int src = __ffs(mco) - 1; mco &= mco - 1;
            float v  = __shfl_sync(0xffffffffu, cost, src);
            int   vx = baseW + src;
            WINS_COST(v, vx);
        }
    }
#undef WINS_IOU
#undef WINS_COST

    if (lane == 0) {
        s_io[wid*5+0]=i0; s_io[wid*5+1]=i1; s_io[wid*5+2]=i2; s_io[wid*5+3]=i3; s_io[wid*5+4]=i4;
        s_cv[wid*5+0]=c0; s_cv[wid*5+1]=c1; s_cv[wid*5+2]=c2; s_cv[wid*5+3]=c3; s_cv[wid*5+4]=c4v;
        s_ci[wid*5+0]=x0; s_ci[wid*5+1]=x1; s_ci[wid*5+2]=x2; s_ci[wid*5+3]=x3; s_ci[wid*5+4]=x4;
    }
    __syncthreads();
    int t = threadIdx.x;
    for (int stride = 4; stride > 0; stride >>= 1) {
        if (t < stride)
            merge_lists(&s_io[t*5], &s_cv[t*5], &s_ci[t*5],
                        &s_io[(t+stride)*5], &s_cv[(t+stride)*5], &s_ci[(t+stride)*5]);
        __syncthreads();
    }
    if (t == 0) {
        float s = 0.f;
        for (int q = 0; q < 5; q++) s += s_io[q];
        int dk = (int)s;
        if (dk < 1) dk = 1;
        if (dk > 5) dk = 5;
        g_dk[j] = dk;
        for (int q = 0; q < 5; q++) g_cand[j * 5 + q] = s_ci[q];
        for (int q = 0; q < dk; q++) {
            int r = s_ci[q];
            atomicMin(&g_minGt[r], j);
            atomicAdd(&g_rowcnt[r], 1);
        }
    }
}

// over-assigned rows: flag + append only.
__global__ void fix_kernel() {
    int i = blockIdx.x * blockDim.x + threadIdx.x;
    if (i >= NP) return;
    if (g_rowcnt[i] > 1) {
        int p = atomicAdd(&g_priorCount, 1);
        if (p < PMAX) {
            g_priorFlag[i] = 1;
            g_priorList[p] = i;
        }
        g_rowcnt[i] = 1;
    }
}

// Gather prior rows into compact scratch AND compute the row argmin.
__global__ void gather_kernel() {
    int p = blockIdx.x;
    if (p >= g_priorCount || p >= PMAX) return;
    int i = g_priorList[p];
    __shared__ float s_v[256];
    __shared__ int   s_j[256];
    float bv = 3.4e38f; int bj = 0x7fffffff;
    for (int j = threadIdx.x; j < NG; j += 256) {
        float v = g_cost[(size_t)j * NP + i];
        g_priorCost[(size_t)p * NG + j] = v;
        if (v < bv) { bv = v; bj = j; }
    }
    s_v[threadIdx.x] = bv; s_j[threadIdx.x] = bj;
    __syncthreads();
    for (int s = 128; s > 0; s >>= 1) {
        if (threadIdx.x < s) {
            float ov = s_v[threadIdx.x + s]; int oj = s_j[threadIdx.x + s];
            if (ov < s_v[threadIdx.x] || (ov == s_v[threadIdx.x] && oj < s_j[threadIdx.x])) {
                s_v[threadIdx.x] = ov; s_j[threadIdx.x] = oj;
            }
        }
        __syncthreads();
    }
    if (threadIdx.x == 0) g_priorCur[p] = s_j[0];
}

// Device-side while-loop + output (single block, 1024 threads), lazy latch.
__global__ void loop_kernel(float* __restrict__ out) {
    __shared__ unsigned s_mb[(NP + 31) / 32];
    __shared__ short s_list[NG], s_sel[NG], s_fb[NG];
    __shared__ short s_pbj[PMAX];
    __shared__ int s_nA, s_nFb, s_newc;
    int tid = threadIdx.x, wid = tid >> 5, lane = tid & 31;
    int P = g_priorCount;
    if (P > PMAX) P = PMAX;

    for (int j = tid; j < NG; j += 1024) {
        int dk = g_dk[j], c = 0;
        for (int q = 0; q < dk; q++) {
            int r = g_cand[j * 5 + q];
            if (!g_priorFlag[r]) c++;
        }
        g_colcnt[j] = c;
    }
    __syncthreads();
    for (int p = tid; p < P; p += 1024) atomicAdd(&g_colcnt[g_priorCur[p]], 1);

    for (int w = tid; w < (NP + 31) / 32; w += 1024) s_mb[w] = 0u;
    __syncthreads();
    for (int i = tid; i < NP; i += 1024)
        if (g_rowcnt[i] > 0) atomicOr(&s_mb[i >> 5], 1u << (i & 31));
    __syncthreads();

    bool conflictEver = false;
    int  lastAcc = 0;

    for (int iter = 0; iter < 4096; iter++) {
        if (tid == 0) { s_nA = 0; s_nFb = 0; s_newc = 0; }
        __syncthreads();
        for (int gg = tid; gg < NG; gg += 1024)
            if (g_colcnt[gg] == 0) { int u = atomicAdd(&s_nA, 1); s_list[u] = (short)gg; }
        __syncthreads();
        int nA = s_nA;
        if (nA == 0) break;

        if (conflictEver) {
            for (int p = wid; p < P; p += 32) {
                float* row = g_priorCost + (size_t)p * NG;
                float bv = 3.4e38f; int bj = 0x7fffffff;
                for (int jj = lane; jj < NG; jj += 32) {
                    float v = row[jj] + 100000.0f;
                    row[jj] = v;
                    if (v < bv || (v == bv && jj < bj)) { bv = v; bj = jj; }
                }
                #pragma unroll
                for (int off = 16; off; off >>= 1) {
                    float ov = __shfl_down_sync(0xffffffffu, bv, off);
                    int   oj = __shfl_down_sync(0xffffffffu, bj, off);
                    if (ov < bv || (ov == bv && oj < bj)) { bv = ov; bj = oj; }
                }
                if (lane == 0) s_pbj[p] = (short)bj;
            }
            lastAcc = iter + 1;
        }

        for (int u = tid; u < nA; u += 1024) {
            int gg = s_list[u];
            int chosen = -1;
            #pragma unroll
            for (int q = 0; q < 5; q++) {
                int r = g_cand[gg * 5 + q];
                if (chosen < 0 && !((s_mb[r >> 5] >> (r & 31)) & 1u)) chosen = r;
            }
            if (chosen < 0) { int f = atomicAdd(&s_nFb, 1); s_fb[f] = (short)u; }
            s_sel[u] = (short)chosen;
        }
        __syncthreads();

        int nFb = s_nFb;
        for (int f = wid; f < nFb; f += 32) {
            int u = s_fb[f]; int gg = s_list[u];
            const float* col = g_cost + (size_t)gg * NP;
            float bv = 3.4e38f; int bi = 0x7fffffff;
            for (int i = lane; i < NP; i += 32) {
                if (!((s_mb[i >> 5] >> (i & 31)) & 1u)) {
                    float v = col[i];
                    if (v < bv || (v == bv && i < bi)) { bv = v; bi = i; }
                }
            }
            #pragma unroll
            for (int off = 16; off; off >>= 1) {
                float ov = __shfl_down_sync(0xffffffffu, bv, off);
                int   oi = __shfl_down_sync(0xffffffffu, bi, off);
                if (ov < bv || (ov == bv && oi < bi)) { bv = ov; bi = oi; }
            }
            if (lane == 0) s_sel[u] = (short)bi;
        }
        __syncthreads();

        for (int u = tid; u < nA; u += 1024) {
            int r = (int)s_sel[u];
            if (r < 0) continue;
            int gg = s_list[u];
            atomicMin(&g_minGt[r], gg);
            int old = atomicAdd(&g_rowcnt[r], 1);
            if (old >= 1) atomicAdd(&s_newc, 1);
            g_colcnt[gg] = 1;
        }
        __syncthreads();
        for (int u = tid; u < nA; u += 1024) {
            int r = (int)s_sel[u];
            if (r >= 0) atomicOr(&s_mb[r >> 5], 1u << (r & 31));
        }
        __syncthreads();

        if (!conflictEver && s_newc > 0) {
            int adds = iter + 1 - lastAcc;
            for (int p = wid; p < P; p += 32) {
                float* row = g_priorCost + (size_t)p * NG;
                float bv = 3.4e38f; int bj = 0x7fffffff;
                for (int jj = lane; jj < NG; jj += 32) {
                    float v = row[jj];
                    #pragma unroll 1
                    for (int t = 0; t < adds; t++) v += 100000.0f;
                    row[jj] = v;
                    if (v < bv || (v == bv && jj < bj)) { bv = v; bj = jj; }
                }
                #pragma unroll
                for (int off = 16; off; off >>= 1) {
                    float ov = __shfl_down_sync(0xffffffffu, bv, off);
                    int   oj = __shfl_down_sync(0xffffffffu, bj, off);
                    if (ov < bv || (ov == bv && oj < bj)) { bv = ov; bj = oj; }
                }
                if (lane == 0) s_pbj[p] = (short)bj;
            }
            lastAcc = iter + 1;
            conflictEver = true;
            __syncthreads();
        }
        if (!conflictEver) { __syncthreads(); continue; }

        for (int p = tid; p < P; p += 1024) {
            int bj = (int)s_pbj[p];
            int cur = g_priorCur[p];
            if (bj != cur) {
                atomicSub(&g_colcnt[cur], 1);
                atomicAdd(&g_colcnt[bj], 1);
                g_priorCur[p] = bj;
            }
        }
        __syncthreads();
    }

    for (int i = tid; i < NP; i += 1024) {
        int fg = g_rowcnt[i] > 0;
        out[i] = fg ? 1.0f : 0.0f;
        int mg = 0;
        if (fg) { int m = g_minGt[i]; if (m != 0x7fffffff) mg = m; }
        out[NP + i] = (float)mg;
    }
    __syncthreads();
    for (int p = tid; p < P; p += 1024)
        out[NP + g_priorList[p]] = (float)g_priorCur[p];
}

extern "C" void kernel_launch(void* const* d_in, const int* in_sizes, int n_in,
                              void* d_out, int out_size) {
    const float* logits = (const float*)d_in[0];
    const float* pb     = (const float*)d_in[1];
    const float* gb     = (const float*)d_in[2];
    const int*   labels = (const int*)  d_in[3];
    const int*   p_h    = (const int*)  d_in[4];
    const int*   p_w    = (const int*)  d_in[5];

    cls_kernel<<<dim3((NP + 255) / 256, NC / 4), 256>>>(logits);
    valid_kernel<<<(NP + 7) / 8, 256>>>(pb, gb, p_h, p_w);
    pair_kernel<<<NG, 256>>>(pb, gb, labels, p_h, p_w);
    fix_kernel<<<(NP + 255) / 256, 256>>>();
    gather_kernel<<<PMAX, 256>>>();
    loop_kernel<<<1, 1024>>>((float*)d_out);
}